// round 15
// baseline (speedup 1.0000x reference)
#include <cuda_runtime.h>
#include <cuda_fp16.h>
#include <cuda_bf16.h>
#include <cstdint>

// Problem constants
#define B_  8
#define N_  512
#define M_  32
#define HA  128
#define HB  64
#define C_  256          // 2*HA
#define BN_ROWS 4096     // B*N
#define ROWS 131072      // B*N*M
#define EPS 1e-5f

// ---------------- scratch ----------------
__device__ unsigned d_Sh [BN_ROWS * HA];      // half2(S_c, S_{c+128})  [4096][128] 2 MB
__device__ unsigned d_P2h[BN_ROWS * HA];      // half2(P2_c, P2_{c+128}) 2 MB
__device__ unsigned d_gated2u[(size_t)ROWS * HA]; // half2(g_j, g_{j+128}) [bn][m][j] 64 MB
__device__ float    d_nbr[BN_ROWS * HA];
__device__ float    d_stats1[512];            // finalized: sum lo@0, sum hi@128, sq lo@256, sq hi@384
__device__ float    d_stats2[256];            // finalized
__device__ float    d_sh1[32 * 512];          // 32-way shards for stats1
__device__ float    d_sh2[32 * 256];          // 32-way shards for stats2
// weight images (built by kP)
__device__ __half        d_W3f[256 * 64];     // fp16 edge weights W[:,256:320]
// Wab images with INTERLEAVED rows: image row u = 2*(ch&127) + (ch>>7),
// so B-tile row pairs (2k, 2k+1) = channels (c, c+128) of the same half-block.
__device__ __nv_bfloat16 d_Wabh[512 * 128];   // rows 0..255: S weights; 256..511: P2 weights
__device__ __nv_bfloat16 d_Wabl[512 * 128];

// ---------------- helpers ----------------
__device__ __forceinline__ unsigned packbf(float a, float b) {
    __nv_bfloat162 t = __floats2bfloat162_rn(a, b);
    return *reinterpret_cast<unsigned*>(&t);
}
__device__ __forceinline__ unsigned packh(float a, float b) {
    __half2 t = __floats2half2_rn(a, b);
    return *reinterpret_cast<unsigned*>(&t);
}
__device__ __forceinline__ uint32_t smem_u32(const void* p) {
    uint32_t a;
    asm("{ .reg .u64 t; cvta.to.shared.u64 t, %1; cvt.u32.u64 %0, t; }" : "=r"(a) : "l"(p));
    return a;
}
__device__ __forceinline__ void ldmx4(unsigned r[4], uint32_t saddr) {
    asm volatile("ldmatrix.sync.aligned.m8n8.x4.shared.b16 {%0,%1,%2,%3}, [%4];"
        : "=r"(r[0]), "=r"(r[1]), "=r"(r[2]), "=r"(r[3]) : "r"(saddr));
}
// bf16 mma (kA)
__device__ __forceinline__ void mma16816(float c[4],
                                         unsigned a0, unsigned a1, unsigned a2, unsigned a3,
                                         unsigned b0, unsigned b1) {
    asm volatile(
        "mma.sync.aligned.m16n8k16.row.col.f32.bf16.bf16.f32 "
        "{%0,%1,%2,%3}, {%4,%5,%6,%7}, {%8,%9}, {%0,%1,%2,%3};\n"
        : "+f"(c[0]), "+f"(c[1]), "+f"(c[2]), "+f"(c[3])
        : "r"(a0), "r"(a1), "r"(a2), "r"(a3), "r"(b0), "r"(b1));
}
// fp16 mma (kB)
__device__ __forceinline__ void mma16816h(float c[4],
                                          unsigned a0, unsigned a1, unsigned a2, unsigned a3,
                                          unsigned b0, unsigned b1) {
    asm volatile(
        "mma.sync.aligned.m16n8k16.row.col.f32.f16.f16.f32 "
        "{%0,%1,%2,%3}, {%4,%5,%6,%7}, {%8,%9}, {%0,%1,%2,%3};\n"
        : "+f"(c[0]), "+f"(c[1]), "+f"(c[2]), "+f"(c[3])
        : "r"(a0), "r"(a1), "r"(a2), "r"(a3), "r"(b0), "r"(b1));
}
__device__ __forceinline__ float fast_sigmoid(float x) {
    float t;
    asm("tanh.approx.f32 %0, %1;" : "=f"(t) : "f"(0.5f * x));
    return fmaf(0.5f, t, 0.5f);
}

// =====================================================================
// Kernel P: build weight images — coalesced, 256 CTAs x 320.
// Wab rows interleaved: u = 2*(ch&127) + (ch>>7).
// =====================================================================
__global__ __launch_bounds__(320) void kP(const float* __restrict__ W) {
    const int ch = blockIdx.x;
    const int t  = threadIdx.x;                 // 0..319
    const float v = W[ch * 320 + t];
    const int u  = 2 * (ch & 127) + (ch >> 7);
    if (t < 128) {                              // S weights: W[ch][0:128]
        const __nv_bfloat16 h = __float2bfloat16_rn(v);
        d_Wabh[(size_t)u * 128 + t] = h;
        d_Wabl[(size_t)u * 128 + t] = __float2bfloat16_rn(v - __bfloat162float(h));
    } else if (t < 256) {                       // P2 weights: W[ch][128:256]
        const __nv_bfloat16 h = __float2bfloat16_rn(v);
        d_Wabh[(size_t)(u + 256) * 128 + (t - 128)] = h;
        d_Wabl[(size_t)(u + 256) * 128 + (t - 128)] = __float2bfloat16_rn(v - __bfloat162float(h));
    } else {
        d_W3f[ch * 64 + (t - 256)] = __float2half_rn(v);
    }
}

// =====================================================================
// Kernel Z: zero stat shards (also launch-order shim so kB is launch #4).
// =====================================================================
__global__ __launch_bounds__(512) void kZ() {
    const int i = blockIdx.x * 512 + threadIdx.x;
    if (i < 32 * 512) d_sh1[i] = 0.f;
    else              d_sh2[i - 32 * 512] = 0.f;
}

// =====================================================================
// Kernel A: Sh/P2h = X@W^T (bf16x3 mma + ldmatrix), PACKED half2 output.
// =====================================================================
#define KA_ST 136
#define KA_SM_XH 0
#define KA_SM_XL (KA_SM_XH + 128 * KA_ST * 2)
#define KA_SM_BH (KA_SM_XL + 128 * KA_ST * 2)
#define KA_SM_BL (KA_SM_BH + 128 * KA_ST * 2)
#define KA_SMEM  (KA_SM_BL + 128 * KA_ST * 2)     // 139264

__global__ __launch_bounds__(256) void kA(const float* __restrict__ X) {
    extern __shared__ char sm[];
    const uint32_t sb = smem_u32(sm);
    const int tid = threadIdx.x;
    const int w = tid >> 5, lane = tid & 31;
    const int gid = lane >> 2, tq = lane & 3;
    const int bx = blockIdx.x & 3;
    const int by = blockIdx.x >> 2;
    const int row0 = by * 128;
    const int c0 = bx * 128;                    // image-row base

    {
        const float4* xs = (const float4*)(X + (size_t)row0 * 128);
#pragma unroll
        for (int i = 0; i < 16; i++) {
            const int idx = tid + i * 256;
            float4 v = xs[idx];
            const int r = idx >> 5, k4 = (idx & 31) * 4;
            float h0 = __bfloat162float(__float2bfloat16_rn(v.x));
            float h1 = __bfloat162float(__float2bfloat16_rn(v.y));
            float h2 = __bfloat162float(__float2bfloat16_rn(v.z));
            float h3 = __bfloat162float(__float2bfloat16_rn(v.w));
            uint2 hu, lu;
            hu.x = packbf(v.x, v.y);           hu.y = packbf(v.z, v.w);
            lu.x = packbf(v.x - h0, v.y - h1); lu.y = packbf(v.z - h2, v.w - h3);
            *(uint2*)(sm + KA_SM_XH + (r * KA_ST + k4) * 2) = hu;
            *(uint2*)(sm + KA_SM_XL + (r * KA_ST + k4) * 2) = lu;
        }
    }
    {
        const uint4* sh = (const uint4*)(d_Wabh + (size_t)c0 * 128);
        const uint4* sl = (const uint4*)(d_Wabl + (size_t)c0 * 128);
#pragma unroll
        for (int i = 0; i < 8; i++) {
            const int idx = tid + i * 256;
            const int r = idx >> 4, q = idx & 15;
            *(uint4*)(sm + KA_SM_BH + (r * KA_ST + q * 8) * 2) = sh[idx];
            *(uint4*)(sm + KA_SM_BL + (r * KA_ST + q * 8) * 2) = sl[idx];
        }
    }
    __syncthreads();

    const int rm0 = (w >> 1) * 32;
    const int n0  = (w & 1) * 64;
    const int mm = lane >> 3, rr = lane & 7;
    const uint32_t aoffb = ((rm0 + (mm & 1) * 8 + rr) * KA_ST + (mm >> 1) * 8) * 2;
    const uint32_t boffb = ((n0  + (mm >> 1) * 8 + rr) * KA_ST + (mm & 1) * 8) * 2;

    float acc[2][8][4];
#pragma unroll
    for (int mt = 0; mt < 2; mt++)
#pragma unroll
        for (int nt = 0; nt < 8; nt++)
#pragma unroll
            for (int q = 0; q < 4; q++) acc[mt][nt][q] = 0.f;

    const uint32_t Au[3] = {sb + KA_SM_XH, sb + KA_SM_XH, sb + KA_SM_XL};
    const uint32_t Bu[3] = {sb + KA_SM_BH, sb + KA_SM_BL, sb + KA_SM_BH};
#pragma unroll
    for (int p = 0; p < 3; p++) {
#pragma unroll
        for (int ks = 0; ks < 8; ks++) {
            const uint32_t kb = ks * 32;
            unsigned af[2][4];
            ldmx4(af[0], Au[p] + aoffb + kb);
            ldmx4(af[1], Au[p] + aoffb + kb + 16 * KA_ST * 2);
#pragma unroll
            for (int ntp = 0; ntp < 4; ntp++) {
                unsigned bf[4];
                ldmx4(bf, Bu[p] + boffb + kb + ntp * (16 * KA_ST * 2));
#pragma unroll
                for (int mt = 0; mt < 2; mt++) {
                    mma16816(acc[mt][ntp * 2 + 0], af[mt][0], af[mt][1], af[mt][2], af[mt][3], bf[0], bf[1]);
                    mma16816(acc[mt][ntp * 2 + 1], af[mt][0], af[mt][1], af[mt][2], af[mt][3], bf[2], bf[3]);
                }
            }
        }
    }

    unsigned* outp = (bx < 2) ? d_Sh : d_P2h;
    const int cb = (bx & 1) * 64;
#pragma unroll
    for (int mt = 0; mt < 2; mt++)
#pragma unroll
        for (int rh = 0; rh < 2; rh++) {
            const int r = row0 + rm0 + mt * 16 + gid + 8 * rh;
#pragma unroll
            for (int nt = 0; nt < 8; nt++) {
                const int c = cb + ((n0 + nt * 8 + 2 * tq) >> 1);
                outp[(size_t)r * 128 + c] =
                    packh(acc[mt][nt][2 * rh], acc[mt][nt][2 * rh + 1]);
            }
        }
}

// =====================================================================
// Kernel B: per CTA = 128 rows, N=256, K=64. 512 threads / 16 warps (4x4).
// Single-pass fp16 mma. After mainloop:
//   gather: cooperative row-coalesced P2h gather into SMEM buf (4 wf/row)
//   phase 1: fragment epilogue reads P2 from SMEM (LDS) + broadcast S
//            (LDG), computes g, overwrites buf slot in place (same thread)
//   phase 2: coalesced column pass — BN1 stats (sharded) + gated store.
// =====================================================================
#define KB_ST 72
#define KB_SM_ADJ  0
#define KB_SM_MASK 512
#define KB_SM_A    1024                          // fp16 [128][72] = 18432
#define KB_SM_B    (KB_SM_A + 128 * KB_ST * 2)   // fp16 [256][72] = 36864
#define KB_SM_DSM  1024                          // reuse A/B region: 128*132*4 = 67584
#define DSM_ST 132
#define KB_SMEM    (KB_SM_DSM + 128 * DSM_ST * 4)   // 68608 (covers both layouts)

__global__ __launch_bounds__(512) void kB(const float* __restrict__ nbr_emb,
                                          const int* __restrict__ adj,
                                          const float* __restrict__ mask) {
    extern __shared__ char sm[];
    const uint32_t sb = smem_u32(sm);
    const int tid = threadIdx.x;
    const int w = tid >> 5, lane = tid & 31;
    const int gid = lane >> 2, tq = lane & 3;
    const int tile = blockIdx.x;                    // 0..1023

    if (tid < 128) {
        const int gbn = tile * 4 + (tid >> 5);
        ((int*)  (sm + KB_SM_ADJ ))[tid] = adj [gbn * 32 + (tid & 31)];
        ((float*)(sm + KB_SM_MASK))[tid] = mask[gbn * 32 + (tid & 31)];
    }
    // load + convert A = nbr_emb tile [128][64] -> fp16
    {
        const float4* xs = (const float4*)(nbr_emb + (size_t)tile * 128 * 64);
#pragma unroll
        for (int i = 0; i < 4; i++) {
            const int idx = tid + i * 512;
            float4 v = xs[idx];
            const int r = idx >> 4, k4 = (idx & 15) * 4;
            uint2 hu;
            hu.x = packh(v.x, v.y);
            hu.y = packh(v.z, v.w);
            *(uint2*)(sm + KB_SM_A + (r * KB_ST + k4) * 2) = hu;
        }
    }
    // copy W3 fp16 image [256][64]
    {
        const uint4* sh = (const uint4*)d_W3f;
#pragma unroll
        for (int i = 0; i < 4; i++) {
            const int idx = tid + i * 512;          // 0..2047 (8 uint4 per row)
            const int r = idx >> 3, q = idx & 7;
            *(uint4*)(sm + KB_SM_B + (r * KB_ST + q * 8) * 2) = sh[idx];
        }
    }
    __syncthreads();

    const int rm0 = (w >> 2) * 32;                  // 4 M-tiles
    const int q4  = (w & 3);                        // warp channel-column
    const int n0  = q4 * 32;                        // low-half base
    const int mm = lane >> 3, rr = lane & 7;
    const uint32_t aoffb = ((rm0 + (mm & 1) * 8 + rr) * KB_ST + (mm >> 1) * 8) * 2;
    const uint32_t boffb = ((n0  + (mm >> 1) * 8 + rr) * KB_ST + (mm & 1) * 8) * 2;

    float acc[2][8][4];
#pragma unroll
    for (int mt = 0; mt < 2; mt++)
#pragma unroll
        for (int nt = 0; nt < 8; nt++)
#pragma unroll
            for (int q = 0; q < 4; q++) acc[mt][nt][q] = 0.f;

    const uint32_t Ab = sb + KB_SM_A;
    const uint32_t Bb = sb + KB_SM_B;
#pragma unroll
    for (int ks = 0; ks < 4; ks++) {
        const uint32_t kb = ks * 32;
        unsigned af[2][4];
        ldmx4(af[0], Ab + aoffb + kb);
        ldmx4(af[1], Ab + aoffb + kb + 16 * KB_ST * 2);
#pragma unroll
        for (int ntp = 0; ntp < 4; ntp++) {
            // ntp 0,1 -> n offsets 0,16 within low half; ntp 2,3 -> +128
            const uint32_t noff = (uint32_t)(((ntp & 1) * 16 + (ntp >> 1) * 128) * KB_ST * 2);
            unsigned bf[4];
            ldmx4(bf, Bb + boffb + kb + noff);
#pragma unroll
            for (int mt = 0; mt < 2; mt++) {
                mma16816h(acc[mt][ntp * 2 + 0], af[mt][0], af[mt][1], af[mt][2], af[mt][3], bf[0], bf[1]);
                mma16816h(acc[mt][ntp * 2 + 1], af[mt][0], af[mt][1], af[mt][2], af[mt][3], bf[2], bf[3]);
            }
        }
    }
    __syncthreads();   // A/B SMEM dead; DSM/gather region reuse safe

    // Gather phase: cooperative row-coalesced P2h gather into buf
    {
        const int* sadj = (const int*)(sm + KB_SM_ADJ);
        unsigned* buf = (unsigned*)(sm + KB_SM_DSM);
        const int rowi = tid >> 5;                 // 0..15
        const int l4   = lane;                     // uint4 index within row
#pragma unroll
        for (int it = 0; it < 8; it++) {
            const int r = it * 16 + rowi;
            const int gbn = tile * 4 + (r >> 5);
            const int batch = gbn >> 9;
            const uint4* src = (const uint4*)(d_P2h + ((size_t)batch * 512 + sadj[r]) * 128);
            uint4 v = src[l4];                     // 32 lanes x 16B = full 512B row
            *(uint4*)&buf[r * DSM_ST + l4 * 4] = v;
        }
    }
    __syncthreads();

    // Phase 1: fragment epilogue — P2 from SMEM, broadcast S from gmem,
    // overwrite buf slot in place with g (same thread reads then writes).
    {
        const float* smask = (const float*)(sm + KB_SM_MASK);
        unsigned* buf = (unsigned*)(sm + KB_SM_DSM);
#pragma unroll
        for (int mt = 0; mt < 2; mt++)
#pragma unroll
            for (int rh = 0; rh < 2; rh++) {
                const int r   = rm0 + mt * 16 + gid + 8 * rh;
                const int gbn = tile * 4 + (r >> 5);
                const unsigned* srow = d_Sh + (size_t)gbn * 128;
                const float mk = smask[r];
#pragma unroll
                for (int np = 0; np < 2; np++)
#pragma unroll
                    for (int h = 0; h < 2; h++) {
                        const int clow = n0 + np * 16 + h * 8 + 2 * tq;
                        const float* aLo = acc[mt][np * 2 + h];
                        const float* aHi = acc[mt][(np + 2) * 2 + h];
                        uint2 sv = *(const uint2*)&srow[clow];
                        uint2 pv = *(const uint2*)&buf[r * DSM_ST + clow];
                        float2 s0v = __half22float2(*reinterpret_cast<__half2*>(&sv.x));
                        float2 s1v = __half22float2(*reinterpret_cast<__half2*>(&sv.y));
                        float2 p0v = __half22float2(*reinterpret_cast<__half2*>(&pv.x));
                        float2 p1v = __half22float2(*reinterpret_cast<__half2*>(&pv.y));
                        float g0 = fmaf(mk, p0v.x, aLo[2 * rh]     + s0v.x);
                        float G0 = fmaf(mk, p0v.y, aHi[2 * rh]     + s0v.y);
                        float g1 = fmaf(mk, p1v.x, aLo[2 * rh + 1] + s1v.x);
                        float G1 = fmaf(mk, p1v.y, aHi[2 * rh + 1] + s1v.y);
                        uint2 stv;
                        stv.x = packh(g0, G0);     // half2(c, c+128)
                        stv.y = packh(g1, G1);     // half2(c+1, c+129)
                        *(uint2*)&buf[r * DSM_ST + clow] = stv;
                    }
            }
    }
    __syncthreads();

    // Phase 2: column pass — BN1 stats (sharded) + coalesced gated store
    {
        const int j  = tid & 127;
        const int qh = tid >> 7;                  // 0..3, 32 rows each
        const unsigned* dsm = (const unsigned*)(sm + KB_SM_DSM);
        unsigned* gout = d_gated2u + (size_t)tile * 128 * 128;
        float s0 = 0.f, q0 = 0.f, s1 = 0.f, q1 = 0.f;
#pragma unroll 8
        for (int r = qh * 32; r < qh * 32 + 32; r++) {
            unsigned v = dsm[r * DSM_ST + j];
            __half2 hv = *reinterpret_cast<__half2*>(&v);
            float g = __low2float(hv), h = __high2float(hv);
            s0 += g; q0 = fmaf(g, g, q0);
            s1 += h; q1 = fmaf(h, h, q1);
            gout[r * 128 + j] = v;
        }
        float* shard = d_sh1 + (tile & 31) * 512;
        atomicAdd(&shard[j],       s0);
        atomicAdd(&shard[j + 128], s1);
        atomicAdd(&shard[256 + j], q0);
        atomicAdd(&shard[384 + j], q1);
    }
}

// =====================================================================
// Kernel R1: finalize stats1 from 32 shards. 1 CTA x 512.
// =====================================================================
__global__ __launch_bounds__(512) void kR1() {
    const int j = threadIdx.x;
    float s = 0.f;
#pragma unroll
    for (int p = 0; p < 32; p++) s += d_sh1[p * 512 + j];
    d_stats1[j] = s;
}

// =====================================================================
// Kernel D: BN1 affine + sigmoid(tanh)*relu, sum over M -> d_nbr.
// BN2 stats to 32-way shards (bn & 31).
// =====================================================================
__global__ __launch_bounds__(256) void kD(const float* __restrict__ gamma_h,
                                          const float* __restrict__ beta_h) {
    __shared__ float2 part[4][64];
    const int bn  = blockIdx.x;
    const int tid = threadIdx.x;
    const int j2  = tid & 63;
    const int h   = tid >> 6;
    const float inv = 1.f / (float)ROWS;

    float sc0[2], sh0[2], sc1[2], sh1[2];
#pragma unroll
    for (int c = 0; c < 2; c++) {
        const int j = 2 * j2 + c;
        float m0 = d_stats1[j] * inv;
        float v0 = d_stats1[256 + j] * inv - m0 * m0;
        sc0[c] = gamma_h[j] * rsqrtf(v0 + EPS);
        sh0[c] = beta_h[j] - m0 * sc0[c];
        float m1 = d_stats1[128 + j] * inv;
        float v1 = d_stats1[384 + j] * inv - m1 * m1;
        sc1[c] = gamma_h[128 + j] * rsqrtf(v1 + EPS);
        sh1[c] = beta_h[128 + j] - m1 * sc1[c];
    }

    const uint2* gp = (const uint2*)d_gated2u + (size_t)bn * 2048 + h * 512 + j2;
    float a0 = 0.f, a1 = 0.f;
#pragma unroll
    for (int i = 0; i < 8; i++) {
        uint2 v = gp[i * 64];
        {
            __half2 hv = *reinterpret_cast<__half2*>(&v.x);
            float f = fmaf(__low2float(hv),  sc0[0], sh0[0]);
            float g = fmaf(__high2float(hv), sc1[0], sh1[0]);
            a0 = fmaf(fast_sigmoid(f), fmaxf(g, 0.f), a0);
        }
        {
            __half2 hv = *reinterpret_cast<__half2*>(&v.y);
            float f = fmaf(__low2float(hv),  sc0[1], sh0[1]);
            float g = fmaf(__high2float(hv), sc1[1], sh1[1]);
            a1 = fmaf(fast_sigmoid(f), fmaxf(g, 0.f), a1);
        }
    }
    part[h][j2] = make_float2(a0, a1);
    __syncthreads();
    if (tid < 64) {
        float2 p0 = part[0][tid], p1 = part[1][tid], p2 = part[2][tid], p3 = part[3][tid];
        float s0 = p0.x + p1.x + p2.x + p3.x;
        float s1 = p0.y + p1.y + p2.y + p3.y;
        *(float2*)&d_nbr[(size_t)bn * 128 + 2 * tid] = make_float2(s0, s1);
        float* shard = d_sh2 + (bn & 31) * 256;
        atomicAdd(&shard[2 * tid],       s0);
        atomicAdd(&shard[2 * tid + 1],   s1);
        atomicAdd(&shard[128 + 2 * tid], s0 * s0);
        atomicAdd(&shard[129 + 2 * tid], s1 * s1);
    }
}

// =====================================================================
// Kernel R2: finalize stats2 from 32 shards. 1 CTA x 256.
// =====================================================================
__global__ __launch_bounds__(256) void kR2() {
    const int j = threadIdx.x;
    float s = 0.f;
#pragma unroll
    for (int p = 0; p < 32; p++) s += d_sh2[p * 256 + j];
    d_stats2[j] = s;
}

// =====================================================================
// Kernel F: out = relu(atom_emb + BN2(nbr_sumed))
// =====================================================================
__global__ __launch_bounds__(128) void kF(const float* __restrict__ atom_emb,
                                          const float* __restrict__ gamma_o,
                                          const float* __restrict__ beta_o,
                                          float* __restrict__ out) {
    const int bn = blockIdx.x;
    const int j  = threadIdx.x;
    const float inv = 1.f / (float)BN_ROWS;

    float mean = d_stats2[j] * inv;
    float var  = d_stats2[128 + j] * inv - mean * mean;
    float sc   = gamma_o[j] * rsqrtf(var + EPS);
    float sh   = beta_o[j] - mean * sc;

    float v = atom_emb[bn * 128 + j] + fmaf(d_nbr[bn * 128 + j], sc, sh);
    out[bn * 128 + j] = fmaxf(v, 0.f);
}

// =====================================================================
extern "C" void kernel_launch(void* const* d_in, const int* in_sizes, int n_in,
                              void* d_out, int out_size) {
    (void)in_sizes; (void)n_in; (void)out_size;
    const float* atom_emb = (const float*)d_in[0];
    const float* nbr_emb  = (const float*)d_in[1];
    const int*   adj      = (const int*)d_in[2];   // jax int64 request -> int32 (x64 disabled)
    const float* mask     = (const float*)d_in[3];
    const float* W        = (const float*)d_in[4];
    const float* gamma_h  = (const float*)d_in[6];
    const float* beta_h   = (const float*)d_in[7];
    const float* gamma_o  = (const float*)d_in[8];
    const float* beta_o   = (const float*)d_in[9];
    float* out = (float*)d_out;

    cudaFuncSetAttribute(kA, cudaFuncAttributeMaxDynamicSharedMemorySize, KA_SMEM);
    cudaFuncSetAttribute(kB, cudaFuncAttributeMaxDynamicSharedMemorySize, KB_SMEM);

    kP<<<256,  320>>>(W);
    kA<<<128,  256, KA_SMEM>>>(atom_emb);
    kZ<<<48,   512>>>();
    kB<<<1024, 512, KB_SMEM>>>(nbr_emb, adj, mask);   // launch #4 — ncu target
    kR1<<<1,   512>>>();
    kD<<<4096, 256>>>(gamma_h, beta_h);
    kR2<<<1,   256>>>();
    kF<<<4096, 128>>>(atom_emb, gamma_o, beta_o, out);
}

// round 16
// speedup vs baseline: 1.1579x; 1.1579x over previous
#include <cuda_runtime.h>
#include <cuda_fp16.h>
#include <cuda_bf16.h>
#include <cstdint>

// Problem constants
#define B_  8
#define N_  512
#define M_  32
#define HA  128
#define HB  64
#define C_  256          // 2*HA
#define BN_ROWS 4096     // B*N
#define ROWS 131072      // B*N*M
#define EPS 1e-5f

// ---------------- scratch ----------------
__device__ unsigned d_Sh [BN_ROWS * HA];      // half2(S_c, S_{c+128})  [4096][128] 2 MB
__device__ unsigned d_P2h[BN_ROWS * HA];      // half2(P2_c, P2_{c+128}) 2 MB
__device__ unsigned d_gated2u[(size_t)ROWS * HA]; // half2(g_j, g_{j+128}) [bn][m][j] 64 MB
__device__ float    d_nbr[BN_ROWS * HA];
__device__ float    d_stats1[512];            // finalized: sum lo@0, sum hi@128, sq lo@256, sq hi@384
__device__ float    d_stats2[256];            // finalized
__device__ float    d_sh1[32 * 512];          // 32-way shards for stats1
__device__ float    d_sh2[32 * 256];          // 32-way shards for stats2
// weight images (built by kP)
__device__ __half        d_W3f[256 * 64];     // fp16 edge weights W[:,256:320]
// Wab images with INTERLEAVED rows: image row u = 2*(ch&127) + (ch>>7).
__device__ __nv_bfloat16 d_Wabh[512 * 128];   // rows 0..255: S weights; 256..511: P2 weights
__device__ __nv_bfloat16 d_Wabl[512 * 128];

// ---------------- helpers ----------------
__device__ __forceinline__ unsigned packbf(float a, float b) {
    __nv_bfloat162 t = __floats2bfloat162_rn(a, b);
    return *reinterpret_cast<unsigned*>(&t);
}
__device__ __forceinline__ unsigned packh(float a, float b) {
    __half2 t = __floats2half2_rn(a, b);
    return *reinterpret_cast<unsigned*>(&t);
}
__device__ __forceinline__ uint32_t smem_u32(const void* p) {
    uint32_t a;
    asm("{ .reg .u64 t; cvta.to.shared.u64 t, %1; cvt.u32.u64 %0, t; }" : "=r"(a) : "l"(p));
    return a;
}
__device__ __forceinline__ void ldmx4(unsigned r[4], uint32_t saddr) {
    asm volatile("ldmatrix.sync.aligned.m8n8.x4.shared.b16 {%0,%1,%2,%3}, [%4];"
        : "=r"(r[0]), "=r"(r[1]), "=r"(r[2]), "=r"(r[3]) : "r"(saddr));
}
// bf16 mma (kA)
__device__ __forceinline__ void mma16816(float c[4],
                                         unsigned a0, unsigned a1, unsigned a2, unsigned a3,
                                         unsigned b0, unsigned b1) {
    asm volatile(
        "mma.sync.aligned.m16n8k16.row.col.f32.bf16.bf16.f32 "
        "{%0,%1,%2,%3}, {%4,%5,%6,%7}, {%8,%9}, {%0,%1,%2,%3};\n"
        : "+f"(c[0]), "+f"(c[1]), "+f"(c[2]), "+f"(c[3])
        : "r"(a0), "r"(a1), "r"(a2), "r"(a3), "r"(b0), "r"(b1));
}
// fp16 mma (kB)
__device__ __forceinline__ void mma16816h(float c[4],
                                          unsigned a0, unsigned a1, unsigned a2, unsigned a3,
                                          unsigned b0, unsigned b1) {
    asm volatile(
        "mma.sync.aligned.m16n8k16.row.col.f32.f16.f16.f32 "
        "{%0,%1,%2,%3}, {%4,%5,%6,%7}, {%8,%9}, {%0,%1,%2,%3};\n"
        : "+f"(c[0]), "+f"(c[1]), "+f"(c[2]), "+f"(c[3])
        : "r"(a0), "r"(a1), "r"(a2), "r"(a3), "r"(b0), "r"(b1));
}
__device__ __forceinline__ float fast_sigmoid(float x) {
    float t;
    asm("tanh.approx.f32 %0, %1;" : "=f"(t) : "f"(0.5f * x));
    return fmaf(0.5f, t, 0.5f);
}

// =====================================================================
// Kernel P: build weight images — coalesced, 256 CTAs x 320.
// =====================================================================
__global__ __launch_bounds__(320) void kP(const float* __restrict__ W) {
    const int ch = blockIdx.x;
    const int t  = threadIdx.x;                 // 0..319
    const float v = W[ch * 320 + t];
    const int u  = 2 * (ch & 127) + (ch >> 7);
    if (t < 128) {                              // S weights: W[ch][0:128]
        const __nv_bfloat16 h = __float2bfloat16_rn(v);
        d_Wabh[(size_t)u * 128 + t] = h;
        d_Wabl[(size_t)u * 128 + t] = __float2bfloat16_rn(v - __bfloat162float(h));
    } else if (t < 256) {                       // P2 weights: W[ch][128:256]
        const __nv_bfloat16 h = __float2bfloat16_rn(v);
        d_Wabh[(size_t)(u + 256) * 128 + (t - 128)] = h;
        d_Wabl[(size_t)(u + 256) * 128 + (t - 128)] = __float2bfloat16_rn(v - __bfloat162float(h));
    } else {
        d_W3f[ch * 64 + (t - 256)] = __float2half_rn(v);
    }
}

// =====================================================================
// Kernel Z: zero stat shards (launch-order shim so kB is launch #4).
// =====================================================================
__global__ __launch_bounds__(512) void kZ() {
    const int i = blockIdx.x * 512 + threadIdx.x;
    if (i < 32 * 512) d_sh1[i] = 0.f;
    else              d_sh2[i - 32 * 512] = 0.f;
}

// =====================================================================
// Kernel A: Sh/P2h = X@W^T (bf16x3 mma + ldmatrix), packed half2 output.
// =====================================================================
#define KA_ST 136
#define KA_SM_XH 0
#define KA_SM_XL (KA_SM_XH + 128 * KA_ST * 2)
#define KA_SM_BH (KA_SM_XL + 128 * KA_ST * 2)
#define KA_SM_BL (KA_SM_BH + 128 * KA_ST * 2)
#define KA_SMEM  (KA_SM_BL + 128 * KA_ST * 2)     // 139264

__global__ __launch_bounds__(256) void kA(const float* __restrict__ X) {
    extern __shared__ char sm[];
    const uint32_t sb = smem_u32(sm);
    const int tid = threadIdx.x;
    const int w = tid >> 5, lane = tid & 31;
    const int gid = lane >> 2, tq = lane & 3;
    const int bx = blockIdx.x & 3;
    const int by = blockIdx.x >> 2;
    const int row0 = by * 128;
    const int c0 = bx * 128;                    // image-row base

    {
        const float4* xs = (const float4*)(X + (size_t)row0 * 128);
#pragma unroll
        for (int i = 0; i < 16; i++) {
            const int idx = tid + i * 256;
            float4 v = xs[idx];
            const int r = idx >> 5, k4 = (idx & 31) * 4;
            float h0 = __bfloat162float(__float2bfloat16_rn(v.x));
            float h1 = __bfloat162float(__float2bfloat16_rn(v.y));
            float h2 = __bfloat162float(__float2bfloat16_rn(v.z));
            float h3 = __bfloat162float(__float2bfloat16_rn(v.w));
            uint2 hu, lu;
            hu.x = packbf(v.x, v.y);           hu.y = packbf(v.z, v.w);
            lu.x = packbf(v.x - h0, v.y - h1); lu.y = packbf(v.z - h2, v.w - h3);
            *(uint2*)(sm + KA_SM_XH + (r * KA_ST + k4) * 2) = hu;
            *(uint2*)(sm + KA_SM_XL + (r * KA_ST + k4) * 2) = lu;
        }
    }
    {
        const uint4* sh = (const uint4*)(d_Wabh + (size_t)c0 * 128);
        const uint4* sl = (const uint4*)(d_Wabl + (size_t)c0 * 128);
#pragma unroll
        for (int i = 0; i < 8; i++) {
            const int idx = tid + i * 256;
            const int r = idx >> 4, q = idx & 15;
            *(uint4*)(sm + KA_SM_BH + (r * KA_ST + q * 8) * 2) = sh[idx];
            *(uint4*)(sm + KA_SM_BL + (r * KA_ST + q * 8) * 2) = sl[idx];
        }
    }
    __syncthreads();

    const int rm0 = (w >> 1) * 32;
    const int n0  = (w & 1) * 64;
    const int mm = lane >> 3, rr = lane & 7;
    const uint32_t aoffb = ((rm0 + (mm & 1) * 8 + rr) * KA_ST + (mm >> 1) * 8) * 2;
    const uint32_t boffb = ((n0  + (mm >> 1) * 8 + rr) * KA_ST + (mm & 1) * 8) * 2;

    float acc[2][8][4];
#pragma unroll
    for (int mt = 0; mt < 2; mt++)
#pragma unroll
        for (int nt = 0; nt < 8; nt++)
#pragma unroll
            for (int q = 0; q < 4; q++) acc[mt][nt][q] = 0.f;

    const uint32_t Au[3] = {sb + KA_SM_XH, sb + KA_SM_XH, sb + KA_SM_XL};
    const uint32_t Bu[3] = {sb + KA_SM_BH, sb + KA_SM_BL, sb + KA_SM_BH};
#pragma unroll
    for (int p = 0; p < 3; p++) {
#pragma unroll
        for (int ks = 0; ks < 8; ks++) {
            const uint32_t kb = ks * 32;
            unsigned af[2][4];
            ldmx4(af[0], Au[p] + aoffb + kb);
            ldmx4(af[1], Au[p] + aoffb + kb + 16 * KA_ST * 2);
#pragma unroll
            for (int ntp = 0; ntp < 4; ntp++) {
                unsigned bf[4];
                ldmx4(bf, Bu[p] + boffb + kb + ntp * (16 * KA_ST * 2));
#pragma unroll
                for (int mt = 0; mt < 2; mt++) {
                    mma16816(acc[mt][ntp * 2 + 0], af[mt][0], af[mt][1], af[mt][2], af[mt][3], bf[0], bf[1]);
                    mma16816(acc[mt][ntp * 2 + 1], af[mt][0], af[mt][1], af[mt][2], af[mt][3], bf[2], bf[3]);
                }
            }
        }
    }

    unsigned* outp = (bx < 2) ? d_Sh : d_P2h;
    const int cb = (bx & 1) * 64;
#pragma unroll
    for (int mt = 0; mt < 2; mt++)
#pragma unroll
        for (int rh = 0; rh < 2; rh++) {
            const int r = row0 + rm0 + mt * 16 + gid + 8 * rh;
#pragma unroll
            for (int nt = 0; nt < 8; nt++) {
                const int c = cb + ((n0 + nt * 8 + 2 * tq) >> 1);
                outp[(size_t)r * 128 + c] =
                    packh(acc[mt][nt][2 * rh], acc[mt][nt][2 * rh + 1]);
            }
        }
}

// =====================================================================
// Kernel B: per CTA = 64 rows (2 nodes), N=256, K=64. 256 threads /
// 8 warps in 2x4 (M x N): per-warp work identical to the proven R14
// shape (32 rows x 64 cols). 2048 CTAs -> 2 CTAs/SM (cross-phase overlap).
// Phase 1 (fragment epilogue, high MLP): packed half2 S/P2 loads,
// g = E + S + mk*P2, stage to DSM. Phase 2: coalesced column pass.
// =====================================================================
#define KB_ST 72
#define KB_SM_ADJ  0                              // 64 ints
#define KB_SM_MASK 256                            // 64 floats
#define KB_SM_A    1024                           // fp16 [64][72] = 9216
#define KB_SM_B    (KB_SM_A + 64 * KB_ST * 2)     // fp16 [256][72] = 36864 -> end 47104
#define KB_SM_DSM  1024                           // reuse: 64*132*4 = 33792 -> end 34816
#define DSM_ST 132
#define KB_SMEM    (KB_SM_B + 256 * KB_ST * 2)    // 47104

__global__ __launch_bounds__(256) void kB(const float* __restrict__ nbr_emb,
                                          const int* __restrict__ adj,
                                          const float* __restrict__ mask) {
    extern __shared__ char sm[];
    const uint32_t sb = smem_u32(sm);
    const int tid = threadIdx.x;
    const int w = tid >> 5, lane = tid & 31;
    const int gid = lane >> 2, tq = lane & 3;
    const int tile = blockIdx.x;                    // 0..2047

    if (tid < 64) {
        const int gbn = tile * 2 + (tid >> 5);
        ((int*)  (sm + KB_SM_ADJ ))[tid] = adj [gbn * 32 + (tid & 31)];
        ((float*)(sm + KB_SM_MASK))[tid] = mask[gbn * 32 + (tid & 31)];
    }
    // load + convert A = nbr_emb tile [64][64] -> fp16
    {
        const float4* xs = (const float4*)(nbr_emb + (size_t)tile * 64 * 64);
#pragma unroll
        for (int i = 0; i < 4; i++) {
            const int idx = tid + i * 256;          // 0..1023 float4s
            float4 v = xs[idx];
            const int r = idx >> 4, k4 = (idx & 15) * 4;
            uint2 hu;
            hu.x = packh(v.x, v.y);
            hu.y = packh(v.z, v.w);
            *(uint2*)(sm + KB_SM_A + (r * KB_ST + k4) * 2) = hu;
        }
    }
    // copy W3 fp16 image [256][64]
    {
        const uint4* sh = (const uint4*)d_W3f;
#pragma unroll
        for (int i = 0; i < 8; i++) {
            const int idx = tid + i * 256;          // 0..2047 (8 uint4 per row)
            const int r = idx >> 3, q = idx & 7;
            *(uint4*)(sm + KB_SM_B + (r * KB_ST + q * 8) * 2) = sh[idx];
        }
    }
    __syncthreads();

    const int rm0 = (w >> 2) * 32;                  // 2 M-tiles (0, 32)
    const int q4  = (w & 3);                        // warp channel-column
    const int n0  = q4 * 32;                        // low-half base
    const int mm = lane >> 3, rr = lane & 7;
    const uint32_t aoffb = ((rm0 + (mm & 1) * 8 + rr) * KB_ST + (mm >> 1) * 8) * 2;
    const uint32_t boffb = ((n0  + (mm >> 1) * 8 + rr) * KB_ST + (mm & 1) * 8) * 2;

    float acc[2][8][4];
#pragma unroll
    for (int mt = 0; mt < 2; mt++)
#pragma unroll
        for (int nt = 0; nt < 8; nt++)
#pragma unroll
            for (int q = 0; q < 4; q++) acc[mt][nt][q] = 0.f;

    const uint32_t Ab = sb + KB_SM_A;
    const uint32_t Bb = sb + KB_SM_B;
#pragma unroll
    for (int ks = 0; ks < 4; ks++) {
        const uint32_t kb = ks * 32;
        unsigned af[2][4];
        ldmx4(af[0], Ab + aoffb + kb);
        ldmx4(af[1], Ab + aoffb + kb + 16 * KB_ST * 2);
#pragma unroll
        for (int ntp = 0; ntp < 4; ntp++) {
            // ntp 0,1 -> n offsets 0,16 within low half; ntp 2,3 -> +128
            const uint32_t noff = (uint32_t)(((ntp & 1) * 16 + (ntp >> 1) * 128) * KB_ST * 2);
            unsigned bf[4];
            ldmx4(bf, Bb + boffb + kb + noff);
#pragma unroll
            for (int mt = 0; mt < 2; mt++) {
                mma16816h(acc[mt][ntp * 2 + 0], af[mt][0], af[mt][1], af[mt][2], af[mt][3], bf[0], bf[1]);
                mma16816h(acc[mt][ntp * 2 + 1], af[mt][0], af[mt][1], af[mt][2], af[mt][3], bf[2], bf[3]);
            }
        }
    }
    __syncthreads();   // A/B SMEM dead; DSM reuse safe

    // Phase 1: fragment epilogue (packed S/P2 loads, high MLP) -> DSM stage
    {
        const int*   sadj  = (const int*)  (sm + KB_SM_ADJ);
        const float* smask = (const float*)(sm + KB_SM_MASK);
        char* dsm = sm + KB_SM_DSM;
#pragma unroll
        for (int mt = 0; mt < 2; mt++)
#pragma unroll
            for (int rh = 0; rh < 2; rh++) {
                const int r   = rm0 + mt * 16 + gid + 8 * rh;   // 0..63
                const int gbn = tile * 2 + (r >> 5);
                const int batch = gbn >> 9;
                const unsigned* srow = d_Sh + (size_t)gbn * 128;
                const unsigned* p2r  = d_P2h + ((size_t)batch * 512 + sadj[r]) * 128;
                const float mk = smask[r];
#pragma unroll
                for (int np = 0; np < 2; np++)
#pragma unroll
                    for (int h = 0; h < 2; h++) {
                        const int clow = n0 + np * 16 + h * 8 + 2 * tq;
                        const float* aLo = acc[mt][np * 2 + h];
                        const float* aHi = acc[mt][(np + 2) * 2 + h];
                        uint2 sv = *(const uint2*)&srow[clow];
                        uint2 pv = *(const uint2*)&p2r[clow];
                        float2 s0v = __half22float2(*reinterpret_cast<__half2*>(&sv.x));
                        float2 s1v = __half22float2(*reinterpret_cast<__half2*>(&sv.y));
                        float2 p0v = __half22float2(*reinterpret_cast<__half2*>(&pv.x));
                        float2 p1v = __half22float2(*reinterpret_cast<__half2*>(&pv.y));
                        float g0 = fmaf(mk, p0v.x, aLo[2 * rh]     + s0v.x);
                        float G0 = fmaf(mk, p0v.y, aHi[2 * rh]     + s0v.y);
                        float g1 = fmaf(mk, p1v.x, aLo[2 * rh + 1] + s1v.x);
                        float G1 = fmaf(mk, p1v.y, aHi[2 * rh + 1] + s1v.y);
                        uint2 stv;
                        stv.x = packh(g0, G0);     // half2(c, c+128)
                        stv.y = packh(g1, G1);     // half2(c+1, c+129)
                        *(uint2*)(dsm + (r * DSM_ST + clow) * 4) = stv;
                    }
            }
    }
    __syncthreads();

    // Phase 2: column pass — BN1 stats (sharded) + coalesced gated store
    {
        const int j  = tid & 127;
        const int qh = tid >> 7;                  // 0..1, 32 rows each
        const unsigned* dsm = (const unsigned*)(sm + KB_SM_DSM);
        unsigned* gout = d_gated2u + (size_t)tile * 64 * 128;
        float s0 = 0.f, q0 = 0.f, s1 = 0.f, q1 = 0.f;
#pragma unroll 8
        for (int r = qh * 32; r < qh * 32 + 32; r++) {
            unsigned v = dsm[r * DSM_ST + j];
            __half2 hv = *reinterpret_cast<__half2*>(&v);
            float g = __low2float(hv), h = __high2float(hv);
            s0 += g; q0 = fmaf(g, g, q0);
            s1 += h; q1 = fmaf(h, h, q1);
            gout[r * 128 + j] = v;
        }
        float* shard = d_sh1 + (tile & 31) * 512;
        atomicAdd(&shard[j],       s0);
        atomicAdd(&shard[j + 128], s1);
        atomicAdd(&shard[256 + j], q0);
        atomicAdd(&shard[384 + j], q1);
    }
}

// =====================================================================
// Kernel R1: finalize stats1 from 32 shards. 1 CTA x 512.
// =====================================================================
__global__ __launch_bounds__(512) void kR1() {
    const int j = threadIdx.x;
    float s = 0.f;
#pragma unroll
    for (int p = 0; p < 32; p++) s += d_sh1[p * 512 + j];
    d_stats1[j] = s;
}

// =====================================================================
// Kernel D: BN1 affine + sigmoid(tanh)*relu, sum over M -> d_nbr.
// BN2 stats to 32-way shards (bn & 31).
// =====================================================================
__global__ __launch_bounds__(256) void kD(const float* __restrict__ gamma_h,
                                          const float* __restrict__ beta_h) {
    __shared__ float2 part[4][64];
    const int bn  = blockIdx.x;
    const int tid = threadIdx.x;
    const int j2  = tid & 63;
    const int h   = tid >> 6;
    const float inv = 1.f / (float)ROWS;

    float sc0[2], sh0[2], sc1[2], sh1[2];
#pragma unroll
    for (int c = 0; c < 2; c++) {
        const int j = 2 * j2 + c;
        float m0 = d_stats1[j] * inv;
        float v0 = d_stats1[256 + j] * inv - m0 * m0;
        sc0[c] = gamma_h[j] * rsqrtf(v0 + EPS);
        sh0[c] = beta_h[j] - m0 * sc0[c];
        float m1 = d_stats1[128 + j] * inv;
        float v1 = d_stats1[384 + j] * inv - m1 * m1;
        sc1[c] = gamma_h[128 + j] * rsqrtf(v1 + EPS);
        sh1[c] = beta_h[128 + j] - m1 * sc1[c];
    }

    const uint2* gp = (const uint2*)d_gated2u + (size_t)bn * 2048 + h * 512 + j2;
    float a0 = 0.f, a1 = 0.f;
#pragma unroll
    for (int i = 0; i < 8; i++) {
        uint2 v = gp[i * 64];
        {
            __half2 hv = *reinterpret_cast<__half2*>(&v.x);
            float f = fmaf(__low2float(hv),  sc0[0], sh0[0]);
            float g = fmaf(__high2float(hv), sc1[0], sh1[0]);
            a0 = fmaf(fast_sigmoid(f), fmaxf(g, 0.f), a0);
        }
        {
            __half2 hv = *reinterpret_cast<__half2*>(&v.y);
            float f = fmaf(__low2float(hv),  sc0[1], sh0[1]);
            float g = fmaf(__high2float(hv), sc1[1], sh1[1]);
            a1 = fmaf(fast_sigmoid(f), fmaxf(g, 0.f), a1);
        }
    }
    part[h][j2] = make_float2(a0, a1);
    __syncthreads();
    if (tid < 64) {
        float2 p0 = part[0][tid], p1 = part[1][tid], p2 = part[2][tid], p3 = part[3][tid];
        float s0 = p0.x + p1.x + p2.x + p3.x;
        float s1 = p0.y + p1.y + p2.y + p3.y;
        *(float2*)&d_nbr[(size_t)bn * 128 + 2 * tid] = make_float2(s0, s1);
        float* shard = d_sh2 + (bn & 31) * 256;
        atomicAdd(&shard[2 * tid],       s0);
        atomicAdd(&shard[2 * tid + 1],   s1);
        atomicAdd(&shard[128 + 2 * tid], s0 * s0);
        atomicAdd(&shard[129 + 2 * tid], s1 * s1);
    }
}

// =====================================================================
// Kernel R2: finalize stats2 from 32 shards. 1 CTA x 256.
// =====================================================================
__global__ __launch_bounds__(256) void kR2() {
    const int j = threadIdx.x;
    float s = 0.f;
#pragma unroll
    for (int p = 0; p < 32; p++) s += d_sh2[p * 256 + j];
    d_stats2[j] = s;
}

// =====================================================================
// Kernel F: out = relu(atom_emb + BN2(nbr_sumed))
// =====================================================================
__global__ __launch_bounds__(128) void kF(const float* __restrict__ atom_emb,
                                          const float* __restrict__ gamma_o,
                                          const float* __restrict__ beta_o,
                                          float* __restrict__ out) {
    const int bn = blockIdx.x;
    const int j  = threadIdx.x;
    const float inv = 1.f / (float)BN_ROWS;

    float mean = d_stats2[j] * inv;
    float var  = d_stats2[128 + j] * inv - mean * mean;
    float sc   = gamma_o[j] * rsqrtf(var + EPS);
    float sh   = beta_o[j] - mean * sc;

    float v = atom_emb[bn * 128 + j] + fmaf(d_nbr[bn * 128 + j], sc, sh);
    out[bn * 128 + j] = fmaxf(v, 0.f);
}

// =====================================================================
extern "C" void kernel_launch(void* const* d_in, const int* in_sizes, int n_in,
                              void* d_out, int out_size) {
    (void)in_sizes; (void)n_in; (void)out_size;
    const float* atom_emb = (const float*)d_in[0];
    const float* nbr_emb  = (const float*)d_in[1];
    const int*   adj      = (const int*)d_in[2];   // jax int64 request -> int32 (x64 disabled)
    const float* mask     = (const float*)d_in[3];
    const float* W        = (const float*)d_in[4];
    const float* gamma_h  = (const float*)d_in[6];
    const float* beta_h   = (const float*)d_in[7];
    const float* gamma_o  = (const float*)d_in[8];
    const float* beta_o   = (const float*)d_in[9];
    float* out = (float*)d_out;

    cudaFuncSetAttribute(kA, cudaFuncAttributeMaxDynamicSharedMemorySize, KA_SMEM);
    cudaFuncSetAttribute(kB, cudaFuncAttributeMaxDynamicSharedMemorySize, KB_SMEM);

    kP<<<256,  320>>>(W);
    kA<<<128,  256, KA_SMEM>>>(atom_emb);
    kZ<<<48,   512>>>();
    kB<<<2048, 256, KB_SMEM>>>(nbr_emb, adj, mask);   // launch #4 — ncu target
    kR1<<<1,   512>>>();
    kD<<<4096, 256>>>(gamma_h, beta_h);
    kR2<<<1,   256>>>();
    kF<<<4096, 128>>>(atom_emb, gamma_o, beta_o, out);
}